// round 3
// baseline (speedup 1.0000x reference)
#include <cuda_runtime.h>
#include <math.h>

#define B_IMGS   64
#define NBLK     4096
#define NLIN     16384
#define NCHR     16384
#define TOPK     100
#define KSEL     128      // exact top-K superset size by logit
#define MTGT     160      // stop narrowing once survivor count <= this
#define NT       512
#define FASTCAP  512

// Output layout (float32), reference return order (*blk, *lin, *chr):
//  blk_data [64,100,4]  @ 0
//  blk_scores [64,100]  @ 25600
//  blk_keep  [64,100]   @ 32000
//  lin_data [64,100,4]  @ 38400
//  lin_scores [64,100]  @ 64000
//  lin_keep  [64,100]   @ 70400
//  chr_data [64,100,16] @ 76800
//  chr_scores [64,100]  @ 179200
//  chr_keep  [64,100]   @ 185600   (total 192000)

struct __align__(16) SharedState {
    unsigned int adj[TOPK][4];          // 16B-aligned rows for uint4 scan
    float sdat[TOPK][16];
    unsigned long long fckey[FASTCAP];  // (prob_bits<<32) | ~idx
    unsigned int ckey[FASTCAP];
    int          cidx[FASTCAP];
    float sval[TOPK];
    int   sidx[TOPK];
    float sbox[TOPK][4];
    float sarea[TOPK];
    float sbelong[TOPK];
    int   skeep[TOPK];
    unsigned int keepw[4];
    int totals[32];
    int cnt;
    int cnt2;
    int flag_any_vk;
    int argmax_idx;
};

template<int LOC>
__device__ __forceinline__ void pp_body(
    SharedState& sm, int level, int b, int tid,
    const float* __restrict__ lb,        // logits for this (b, level)
    const float* __restrict__ blk_raw,
    const float* __restrict__ lin_raw,
    const float* __restrict__ chr_raw,
    const float* __restrict__ tsz,
    float* __restrict__ out)
{
    const int N = LOC * NT;

    // ---- load logits -> monotone uint keys (registers) ----
    unsigned int lk[LOC];
#pragma unroll
    for (int r = 0; r < LOC; ++r) {
        unsigned int u = __float_as_uint(lb[tid + r * NT]);
        lk[r] = u ^ (((unsigned int)((int)u >> 31)) | 0x80000000u);
    }

    if (tid < 32) sm.totals[tid] = 0;
    if (tid == 0) { sm.cnt = 0; sm.cnt2 = 0; sm.flag_any_vk = 0; sm.argmax_idx = 0; }
    __syncthreads();

    // ---- phase 1: bitwise binary search on registers, exit when survivors <= FASTCAP ----
    unsigned int prefix = 0u;
    int cnt_cur = N;
    int bit = 31;
    for (; bit >= 0; --bit) {
        if (cnt_cur <= FASTCAP) break;
        unsigned int cand = prefix | (1u << bit);
        int c = 0;
#pragma unroll
        for (int r = 0; r < LOC; ++r) c += (lk[r] >= cand) ? 1 : 0;
#pragma unroll
        for (int off = 16; off > 0; off >>= 1) c += __shfl_down_sync(0xFFFFFFFFu, c, off);
        if ((tid & 31) == 0 && c) atomicAdd(&sm.totals[bit], c);
        __syncthreads();
        int tot = sm.totals[bit];
        if (tot >= KSEL) { prefix = cand; cnt_cur = tot; }
    }

    // ---- phase 2: gather survivors (key >= prefix) to shared, 1/thread ----
#pragma unroll
    for (int r = 0; r < LOC; ++r) {
        if (lk[r] >= prefix) {
            int p = atomicAdd(&sm.cnt, 1);
            if (p < FASTCAP) { sm.ckey[p] = lk[r]; sm.cidx[p] = tid + r * NT; }
        }
    }
    __syncthreads();
    const int cg = min(sm.cnt, FASTCAP);
    const unsigned int mykey = (tid < cg) ? sm.ckey[tid] : 0u;
    const int myidx = (tid < cg) ? sm.cidx[tid] : 0;

    // ---- phase 3: continue narrowing until survivor count <= MTGT ----
    int cnt_m = cg;
    for (; bit >= 0 && cnt_m > MTGT; --bit) {
        unsigned int cand = prefix | (1u << bit);
        int c = __syncthreads_count((tid < cg) && (mykey >= cand));
        if (c >= KSEL) { prefix = cand; cnt_m = c; }
    }

    // ---- phase 4: compact final survivors, exact f32 sigmoid, composite key ----
    if (tid < cg && mykey >= prefix) {
        int p = atomicAdd(&sm.cnt2, 1);
        unsigned int u = mykey ^ ((mykey & 0x80000000u) ? 0x80000000u : 0xFFFFFFFFu);
        float x = __uint_as_float(u);
        double e = exp(-(double)x);
        float prob = (float)(1.0 / (1.0 + e));
        sm.fckey[p] = ((unsigned long long)__float_as_uint(prob) << 32)
                      | (unsigned int)(~(unsigned int)myidx);
    }
    __syncthreads();
    const int M = min(sm.cnt2, FASTCAP);   // >= 128 guaranteed (prefix count >= KSEL)

    // ---- rank by composite key desc == (prob desc, index asc) ----
    if (tid < M) {
        const unsigned long long mk = sm.fckey[tid];
        int rank = 0;
        for (int j = 0; j < M; ++j) rank += (sm.fckey[j] > mk) ? 1 : 0;
        if (rank < TOPK) {
            sm.sval[rank] = __uint_as_float((unsigned int)(mk >> 32));
            sm.sidx[rank] = (int)(~(unsigned int)(mk & 0xFFFFFFFFu));
        }
    }
    __syncthreads();

    const float hh = tsz[2 * b + 0];   // img_h
    const float ww = tsz[2 * b + 1];   // img_w

    // ---- per-detection geometry ----
    if (tid < TOPK) {
        const int k  = tid;
        const int si = sm.sidx[k];
        float x1, y1, x2, y2;

        if (level == 2) {
            const float4* rp4 = (const float4*)(chr_raw + ((size_t)b * NCHR + (size_t)si) * 16);
            float ctrl[16];
#pragma unroll
            for (int q = 0; q < 4; ++q) {
                float4 v = rp4[q];
                ctrl[4 * q + 0] = v.x * hh;
                ctrl[4 * q + 1] = v.y * ww;
                ctrl[4 * q + 2] = v.z * hh;
                ctrl[4 * q + 3] = v.w * ww;
            }
            float mnx = 1e30f, mny = 1e30f, mxx = -1e30f, mxy = -1e30f;
#pragma unroll
            for (int s = 0; s < 10; ++s) {
                float t  = (float)s * (1.0f / 9.0f);
                float ti = 1.0f - t;
                float b0 = ti * ti * ti;
                float b1 = 3.0f * t * ti * ti;
                float b2 = 3.0f * t * t * ti;
                float b3 = t * t * t;
                float xt = b0 * ctrl[0] + b1 * ctrl[2]  + b2 * ctrl[4]  + b3 * ctrl[6];
                float yt = b0 * ctrl[1] + b1 * ctrl[3]  + b2 * ctrl[5]  + b3 * ctrl[7];
                float xb = b0 * ctrl[8] + b1 * ctrl[10] + b2 * ctrl[12] + b3 * ctrl[14];
                float yb = b0 * ctrl[9] + b1 * ctrl[11] + b2 * ctrl[13] + b3 * ctrl[15];
                mnx = fminf(mnx, fminf(xt, xb));
                mny = fminf(mny, fminf(yt, yb));
                mxx = fmaxf(mxx, fmaxf(xt, xb));
                mxy = fmaxf(mxy, fmaxf(yt, yb));
            }
            x1 = mnx; y1 = mny; x2 = mxx; y2 = mxy;
#pragma unroll
            for (int j = 0; j < 16; ++j) sm.sdat[k][j] = ctrl[j];
        } else {
            const float4* rp4 = (level == 0)
                ? (const float4*)(blk_raw + ((size_t)b * NBLK + (size_t)si) * 4)
                : (const float4*)(lin_raw + ((size_t)b * NLIN + (size_t)si) * 4);
            float4 v = rp4[0];
            x1 = (v.x - 0.5f * v.z) * ww;
            y1 = (v.y - 0.5f * v.w) * hh;
            x2 = (v.x + 0.5f * v.z) * ww;
            y2 = (v.y + 0.5f * v.w) * hh;
            if (level == 0) {
                x1 = fminf(fmaxf(x1, 0.0f), ww);
                y1 = fminf(fmaxf(y1, 0.0f), hh);
                x2 = fminf(fmaxf(x2, 0.0f), ww);
                y2 = fminf(fmaxf(y2, 0.0f), hh);
            }
            sm.sdat[k][0] = x1; sm.sdat[k][1] = y1;
            sm.sdat[k][2] = x2; sm.sdat[k][3] = y2;
        }

        sm.sbox[k][0] = x1; sm.sbox[k][1] = y1;
        sm.sbox[k][2] = x2; sm.sbox[k][3] = y2;
        sm.sarea[k] = (x2 - x1) * (y2 - y1);

        bool kp   = sm.sval[k] > 0.1f;
        bool anyk = sm.sval[0] > 0.1f;     // desc-sorted => any() == first > thr
        if (!anyk) kp = (k == 0);
        sm.skeep[k] = kp ? 1 : 0;

        if (level > 0) {
            const float4* pr4 = (level == 1)
                ? (const float4*)(blk_raw + ((size_t)b * NBLK + (size_t)(si >> 2)) * 4)  // ef=4
                : (const float4*)(lin_raw + ((size_t)b * NLIN + (size_t)si) * 4);        // ef=1
            float4 p = pr4[0];
            float px1 = (p.x - 0.5f * p.z) * ww;
            float py1 = (p.y - 0.5f * p.w) * hh;
            float px2 = (p.x + 0.5f * p.z) * ww;
            float py2 = (p.y + 0.5f * p.w) * hh;
            float ix1 = fmaxf(x1, px1);
            float iy1 = fmaxf(y1, py1);
            float ix2 = fminf(x2, px2);
            float iy2 = fminf(y2, py2);
            float inter = fmaxf(ix2 - ix1, 0.0f) * fmaxf(iy2 - iy1, 0.0f);
            float carea = (x2 - x1) * (y2 - y1);
            sm.sbelong[k] = inter / (carea + 1e-6f);
        }
    }
    __syncthreads();

    // ---- belong validity + fallback (lines / chars) ----
    if (level > 0) {
        if (tid == 0) {
            int any = 0;
            float best = -__int_as_float(0x7f800000);  // -inf
            int bi = 0;
            for (int k2 = 0; k2 < TOPK; ++k2) {
                if (sm.skeep[k2]) {
                    float bl = sm.sbelong[k2];
                    if (bl > best) { best = bl; bi = k2; }
                    if (bl > 0.6f) any = 1;
                }
            }
            sm.flag_any_vk = any;
            sm.argmax_idx  = bi;
        }
        __syncthreads();
        if (tid < TOPK) {
            bool valid = sm.sbelong[tid] > 0.6f;
            if (!sm.flag_any_vk) valid = (tid == sm.argmax_idx);
            if (!valid) sm.skeep[tid] = 0;
        }
        __syncthreads();
    }

    // ---- NMS: build adjacency bitmask rows in parallel ----
    {
        const int warp = tid >> 5, lane = tid & 31;
        for (int task = warp; task < TOPK * 4; task += NT / 32) {
            const int i = task >> 2, w = task & 3;
            const int j = w * 32 + lane;
            bool pred = false;
            if (j < TOPK && j > i) {
                float ix1 = fmaxf(sm.sbox[i][0], sm.sbox[j][0]);
                float iy1 = fmaxf(sm.sbox[i][1], sm.sbox[j][1]);
                float ix2 = fminf(sm.sbox[i][2], sm.sbox[j][2]);
                float iy2 = fminf(sm.sbox[i][3], sm.sbox[j][3]);
                float inter = fmaxf(ix2 - ix1, 0.0f) * fmaxf(iy2 - iy1, 0.0f);
                float iou = inter / (sm.sarea[i] + sm.sarea[j] - inter);
                pred = iou > 0.1f;    // NaN-safe false, matches JAX
            }
            unsigned int m = __ballot_sync(0xFFFFFFFFu, pred);
            if (lane == 0) sm.adj[i][w] = m;
        }
        if (tid < 128) {
            bool kp = (tid < TOPK) && (sm.skeep[tid] != 0);
            unsigned int m = __ballot_sync(0xFFFFFFFFu, kp);
            if ((tid & 31) == 0) sm.keepw[tid >> 5] = m;
        }
    }
    __syncthreads();

    // ---- sequential suppression scan: single thread, uint4 rows, branchless ----
    if (tid == 0) {
        unsigned int k0 = sm.keepw[0], k1 = sm.keepw[1], k2 = sm.keepw[2], k3 = sm.keepw[3];
        const uint4* adj4 = (const uint4*)sm.adj;
#pragma unroll
        for (int i = 0; i < TOPK; ++i) {
            unsigned int ki = (i < 32) ? k0 : (i < 64) ? k1 : (i < 96) ? k2 : k3;
            unsigned int bm = (unsigned int)(-(int)((ki >> (i & 31)) & 1u));
            uint4 a = adj4[i];
            k0 &= ~(a.x & bm);
            k1 &= ~(a.y & bm);
            k2 &= ~(a.z & bm);
            k3 &= ~(a.w & bm);
        }
        sm.keepw[0] = k0; sm.keepw[1] = k1; sm.keepw[2] = k2; sm.keepw[3] = k3;
    }
    __syncthreads();
    if (tid < TOPK) sm.skeep[tid] = (sm.keepw[tid >> 5] >> (tid & 31)) & 1u;
    __syncthreads();

    // ---- write outputs ----
    size_t data_off, score_off, keep_off; int D;
    if (level == 0)      { D = 4;  data_off = 0;      score_off = 25600;  keep_off = 32000;  }
    else if (level == 1) { D = 4;  data_off = 38400;  score_off = 64000;  keep_off = 70400;  }
    else                 { D = 16; data_off = 76800;  score_off = 179200; keep_off = 185600; }

    float* dp = out + data_off + (size_t)b * TOPK * D;
    for (int idx = tid; idx < TOPK * D; idx += NT) {
        int k = idx / D;
        dp[idx] = sm.skeep[k] ? sm.sdat[k][idx - k * D] : 0.0f;
    }
    if (tid < TOPK) {
        out[score_off + (size_t)b * TOPK + tid] = sm.skeep[tid] ? sm.sval[tid] : 0.0f;
        out[keep_off  + (size_t)b * TOPK + tid] = sm.skeep[tid] ? 1.0f : 0.0f;
    }
}

__global__ void __launch_bounds__(NT)
postprocess_kernel(const float* __restrict__ blk_logit,
                   const float* __restrict__ lin_logit,
                   const float* __restrict__ chr_logit,
                   const float* __restrict__ blk_raw,
                   const float* __restrict__ lin_raw,
                   const float* __restrict__ chr_raw,
                   const float* __restrict__ tsz,
                   float* __restrict__ out)
{
    __shared__ SharedState sm;
    const int b   = blockIdx.x;
    const int ly  = blockIdx.y;    // 0: blk+lin, 1: chr
    const int tid = threadIdx.x;

    if (ly == 0) {
        pp_body<8>(sm, 0, b, tid, blk_logit + (size_t)b * NBLK,
                   blk_raw, lin_raw, chr_raw, tsz, out);
        __syncthreads();
        pp_body<32>(sm, 1, b, tid, lin_logit + (size_t)b * NLIN,
                    blk_raw, lin_raw, chr_raw, tsz, out);
    } else {
        pp_body<32>(sm, 2, b, tid, chr_logit + (size_t)b * NCHR,
                    blk_raw, lin_raw, chr_raw, tsz, out);
    }
}

extern "C" void kernel_launch(void* const* d_in, const int* in_sizes, int n_in,
                              void* d_out, int out_size) {
    (void)in_sizes; (void)n_in; (void)out_size;
    postprocess_kernel<<<dim3(B_IMGS, 2), NT>>>(
        (const float*)d_in[0],   // pred_block_logits
        (const float*)d_in[1],   // pred_line_logits
        (const float*)d_in[2],   // pred_char_logits
        (const float*)d_in[3],   // pred_block
        (const float*)d_in[4],   // pred_line
        (const float*)d_in[5],   // pred_char
        (const float*)d_in[6],   // target_sizes
        (float*)d_out);
}

// round 4
// speedup vs baseline: 1.4205x; 1.4205x over previous
#include <cuda_runtime.h>
#include <math.h>

#define B_IMGS   64
#define NBLK     4096
#define NLIN     16384
#define NCHR     16384
#define TOPK     100
#define KSEL     128      // exact top-K superset size by logit
#define MTGT     160      // stop narrowing once survivor count <= this
#define NT       512
#define FASTCAP  512

// Output layout (float32), reference return order (*blk, *lin, *chr):
//  blk_data [64,100,4]  @ 0       blk_scores @ 25600   blk_keep @ 32000
//  lin_data [64,100,4]  @ 38400   lin_scores @ 64000   lin_keep @ 70400
//  chr_data [64,100,16] @ 76800   chr_scores @ 179200  chr_keep @ 185600

struct __align__(16) SharedState {
    unsigned int adj[TOPK][4];          // 16B rows for uint4 scan
    float4 sdat4[TOPK][4];              // data rows (16 floats max, float4 access)
    float4 sbox4[TOPK];
    unsigned long long fckey[FASTCAP];  // (prob_bits<<32) | ~idx
    unsigned int ckey[FASTCAP];
    int          cidx[FASTCAP];
    float sval[TOPK];
    int   sidx[TOPK];
    float sarea[TOPK];
    float sbelong[TOPK];
    int   skeep[TOPK];
    unsigned int keepw[4];
    int totals[32];
    int cnt;
    int cnt2;
    int flag_any_vk;
    int argmax_idx;
};

template<int LOC, int LEVEL>
__device__ __forceinline__ void pp_body(
    SharedState& sm, int b, int tid,
    const float* __restrict__ lb,        // logits for this (b, level)
    const float* __restrict__ blk_raw,
    const float* __restrict__ lin_raw,
    const float* __restrict__ chr_raw,
    const float* __restrict__ tsz,
    float* __restrict__ out)
{
    const int N = LOC * NT;

    // ---- load logits via float4 -> monotone uint keys (registers) ----
    // element index for lk[4*r4 + c] is 4*(tid + r4*NT) + c
    unsigned int lk[LOC];
    {
        const float4* lb4 = (const float4*)lb;
#pragma unroll
        for (int r4 = 0; r4 < LOC / 4; ++r4) {
            float4 v = lb4[tid + r4 * NT];
            unsigned int u0 = __float_as_uint(v.x);
            unsigned int u1 = __float_as_uint(v.y);
            unsigned int u2 = __float_as_uint(v.z);
            unsigned int u3 = __float_as_uint(v.w);
            lk[4 * r4 + 0] = u0 ^ (((unsigned int)((int)u0 >> 31)) | 0x80000000u);
            lk[4 * r4 + 1] = u1 ^ (((unsigned int)((int)u1 >> 31)) | 0x80000000u);
            lk[4 * r4 + 2] = u2 ^ (((unsigned int)((int)u2 >> 31)) | 0x80000000u);
            lk[4 * r4 + 3] = u3 ^ (((unsigned int)((int)u3 >> 31)) | 0x80000000u);
        }
    }

    if (tid < 32) sm.totals[tid] = 0;
    if (tid == 0) { sm.cnt = 0; sm.cnt2 = 0; sm.flag_any_vk = 0; sm.argmax_idx = 0; }
    __syncthreads();

    // ---- phase 1: bitwise binary search on registers, exit when survivors <= FASTCAP ----
    unsigned int prefix = 0u;
    int cnt_cur = N;
    int bit = 31;
    for (; bit >= 0; --bit) {
        if (cnt_cur <= FASTCAP) break;
        unsigned int cand = prefix | (1u << bit);
        unsigned int c = 0;
#pragma unroll
        for (int r = 0; r < LOC; ++r) c += (lk[r] >= cand) ? 1u : 0u;
        c = __reduce_add_sync(0xFFFFFFFFu, c);
        if ((tid & 31) == 0 && c) atomicAdd(&sm.totals[bit], (int)c);
        __syncthreads();
        int tot = sm.totals[bit];
        if (tot >= KSEL) { prefix = cand; cnt_cur = tot; }
    }

    // ---- phase 2: gather survivors (key >= prefix) to shared, 1/thread ----
#pragma unroll
    for (int r4 = 0; r4 < LOC / 4; ++r4) {
#pragma unroll
        for (int c = 0; c < 4; ++c) {
            unsigned int k = lk[4 * r4 + c];
            if (k >= prefix) {
                int p = atomicAdd(&sm.cnt, 1);
                if (p < FASTCAP) { sm.ckey[p] = k; sm.cidx[p] = 4 * (tid + r4 * NT) + c; }
            }
        }
    }
    __syncthreads();
    const int cg = min(sm.cnt, FASTCAP);
    const unsigned int mykey = (tid < cg) ? sm.ckey[tid] : 0u;
    const int myidx = (tid < cg) ? sm.cidx[tid] : 0;

    // ---- phase 3: continue narrowing until survivor count <= MTGT ----
    int cnt_m = cg;
    for (; bit >= 0 && cnt_m > MTGT; --bit) {
        unsigned int cand = prefix | (1u << bit);
        int c = __syncthreads_count((tid < cg) && (mykey >= cand));
        if (c >= KSEL) { prefix = cand; cnt_m = c; }
    }

    // ---- phase 4: compact final survivors, exact f32 sigmoid, composite key ----
    if (tid < cg && mykey >= prefix) {
        int p = atomicAdd(&sm.cnt2, 1);
        unsigned int u = mykey ^ ((mykey & 0x80000000u) ? 0x80000000u : 0xFFFFFFFFu);
        float x = __uint_as_float(u);
        double e = exp(-(double)x);
        float prob = (float)(1.0 / (1.0 + e));
        sm.fckey[p] = ((unsigned long long)__float_as_uint(prob) << 32)
                      | (unsigned int)(~(unsigned int)myidx);
    }
    __syncthreads();
    const int M = min(sm.cnt2, FASTCAP);   // >= 128 (prefix count >= KSEL)

    // ---- rank by composite key desc == (prob desc, index asc) ----
    if (tid < M) {
        const unsigned long long mk = sm.fckey[tid];
        int rank = 0;
        for (int j = 0; j < M; ++j) rank += (sm.fckey[j] > mk) ? 1 : 0;
        if (rank < TOPK) {
            sm.sval[rank] = __uint_as_float((unsigned int)(mk >> 32));
            sm.sidx[rank] = (int)(~(unsigned int)(mk & 0xFFFFFFFFu));
        }
    }
    __syncthreads();

    const float hh = tsz[2 * b + 0];   // img_h
    const float ww = tsz[2 * b + 1];   // img_w

    // ---- char level: spread scattered ctrl-point gather over 400 threads ----
    if (LEVEL == 2) {
        if (tid < TOPK * 4) {
            const int k = tid >> 2, q = tid & 3;
            const int si = sm.sidx[k];
            float4 v = ((const float4*)(chr_raw + ((size_t)b * NCHR + (size_t)si) * 16))[q];
            v.x *= hh; v.y *= ww; v.z *= hh; v.w *= ww;
            sm.sdat4[k][q] = v;
        }
        __syncthreads();
    }

    // ---- per-detection geometry ----
    if (tid < TOPK) {
        const int k  = tid;
        const int si = sm.sidx[k];
        float x1, y1, x2, y2;
        float4 p;   // parent box raw (lines/chars) — hoisted load

        if (LEVEL == 1) {
            p = ((const float4*)(blk_raw + ((size_t)b * NBLK + (size_t)(si >> 2)) * 4))[0];
        } else if (LEVEL == 2) {
            p = ((const float4*)(lin_raw + ((size_t)b * NLIN + (size_t)si) * 4))[0];
        }

        if (LEVEL == 2) {
            float ctrl[16];
#pragma unroll
            for (int q = 0; q < 4; ++q) {
                float4 v = sm.sdat4[k][q];
                ctrl[4 * q + 0] = v.x; ctrl[4 * q + 1] = v.y;
                ctrl[4 * q + 2] = v.z; ctrl[4 * q + 3] = v.w;
            }
            float mnx = 1e30f, mny = 1e30f, mxx = -1e30f, mxy = -1e30f;
#pragma unroll
            for (int s = 0; s < 10; ++s) {
                float t  = (float)s * (1.0f / 9.0f);
                float ti = 1.0f - t;
                float b0 = ti * ti * ti;
                float b1 = 3.0f * t * ti * ti;
                float b2 = 3.0f * t * t * ti;
                float b3 = t * t * t;
                float xt = b0 * ctrl[0] + b1 * ctrl[2]  + b2 * ctrl[4]  + b3 * ctrl[6];
                float yt = b0 * ctrl[1] + b1 * ctrl[3]  + b2 * ctrl[5]  + b3 * ctrl[7];
                float xb = b0 * ctrl[8] + b1 * ctrl[10] + b2 * ctrl[12] + b3 * ctrl[14];
                float yb = b0 * ctrl[9] + b1 * ctrl[11] + b2 * ctrl[13] + b3 * ctrl[15];
                mnx = fminf(mnx, fminf(xt, xb));
                mny = fminf(mny, fminf(yt, yb));
                mxx = fmaxf(mxx, fmaxf(xt, xb));
                mxy = fmaxf(mxy, fmaxf(yt, yb));
            }
            x1 = mnx; y1 = mny; x2 = mxx; y2 = mxy;
        } else {
            float4 v = (LEVEL == 0)
                ? ((const float4*)(blk_raw + ((size_t)b * NBLK + (size_t)si) * 4))[0]
                : ((const float4*)(lin_raw + ((size_t)b * NLIN + (size_t)si) * 4))[0];
            x1 = (v.x - 0.5f * v.z) * ww;
            y1 = (v.y - 0.5f * v.w) * hh;
            x2 = (v.x + 0.5f * v.z) * ww;
            y2 = (v.y + 0.5f * v.w) * hh;
            if (LEVEL == 0) {
                x1 = fminf(fmaxf(x1, 0.0f), ww);
                y1 = fminf(fmaxf(y1, 0.0f), hh);
                x2 = fminf(fmaxf(x2, 0.0f), ww);
                y2 = fminf(fmaxf(y2, 0.0f), hh);
            }
            float4 d; d.x = x1; d.y = y1; d.z = x2; d.w = y2;
            sm.sdat4[k][0] = d;
        }

        float4 bx; bx.x = x1; bx.y = y1; bx.z = x2; bx.w = y2;
        sm.sbox4[k] = bx;
        sm.sarea[k] = (x2 - x1) * (y2 - y1);

        bool kp   = sm.sval[k] > 0.1f;
        bool anyk = sm.sval[0] > 0.1f;     // desc-sorted => any() == first > thr
        if (!anyk) kp = (k == 0);
        sm.skeep[k] = kp ? 1 : 0;

        if (LEVEL > 0) {
            float px1 = (p.x - 0.5f * p.z) * ww;
            float py1 = (p.y - 0.5f * p.w) * hh;
            float px2 = (p.x + 0.5f * p.z) * ww;
            float py2 = (p.y + 0.5f * p.w) * hh;
            float ix1 = fmaxf(x1, px1);
            float iy1 = fmaxf(y1, py1);
            float ix2 = fminf(x2, px2);
            float iy2 = fminf(y2, py2);
            float inter = fmaxf(ix2 - ix1, 0.0f) * fmaxf(iy2 - iy1, 0.0f);
            float carea = (x2 - x1) * (y2 - y1);
            sm.sbelong[k] = inter / (carea + 1e-6f);
        }
    }
    __syncthreads();

    // ---- belong validity + fallback (lines / chars) ----
    if (LEVEL > 0) {
        if (tid == 0) {
            int any = 0;
            float best = -__int_as_float(0x7f800000);  // -inf
            int bi = 0;
            for (int k2 = 0; k2 < TOPK; ++k2) {
                if (sm.skeep[k2]) {
                    float bl = sm.sbelong[k2];
                    if (bl > best) { best = bl; bi = k2; }
                    if (bl > 0.6f) any = 1;
                }
            }
            sm.flag_any_vk = any;
            sm.argmax_idx  = bi;
        }
        __syncthreads();
        if (tid < TOPK) {
            bool valid = sm.sbelong[tid] > 0.6f;
            if (!sm.flag_any_vk) valid = (tid == sm.argmax_idx);
            if (!valid) sm.skeep[tid] = 0;
        }
        __syncthreads();
    }

    // ---- NMS: build adjacency bitmask rows in parallel ----
    {
        const int warp = tid >> 5, lane = tid & 31;
        for (int task = warp; task < TOPK * 4; task += NT / 32) {
            const int i = task >> 2, w = task & 3;
            const int j = w * 32 + lane;
            bool pred = false;
            if (j < TOPK && j > i) {
                float4 bi_ = sm.sbox4[i];
                float4 bj_ = sm.sbox4[j];
                float ix1 = fmaxf(bi_.x, bj_.x);
                float iy1 = fmaxf(bi_.y, bj_.y);
                float ix2 = fminf(bi_.z, bj_.z);
                float iy2 = fminf(bi_.w, bj_.w);
                float inter = fmaxf(ix2 - ix1, 0.0f) * fmaxf(iy2 - iy1, 0.0f);
                float iou = inter / (sm.sarea[i] + sm.sarea[j] - inter);
                pred = iou > 0.1f;    // NaN-safe false, matches JAX
            }
            unsigned int m = __ballot_sync(0xFFFFFFFFu, pred);
            if (lane == 0) sm.adj[i][w] = m;
        }
        if (tid < 128) {
            bool kp = (tid < TOPK) && (sm.skeep[tid] != 0);
            unsigned int m = __ballot_sync(0xFFFFFFFFu, kp);
            if ((tid & 31) == 0) sm.keepw[tid >> 5] = m;
        }
    }
    __syncthreads();

    // ---- sequential suppression scan: single thread, uint4 rows, branchless ----
    if (tid == 0) {
        unsigned int k0 = sm.keepw[0], k1 = sm.keepw[1], k2 = sm.keepw[2], k3 = sm.keepw[3];
        const uint4* adj4 = (const uint4*)sm.adj;
#pragma unroll
        for (int i = 0; i < TOPK; ++i) {
            unsigned int ki = (i < 32) ? k0 : (i < 64) ? k1 : (i < 96) ? k2 : k3;
            unsigned int bm = (unsigned int)(-(int)((ki >> (i & 31)) & 1u));
            uint4 a = adj4[i];
            k0 &= ~(a.x & bm);
            k1 &= ~(a.y & bm);
            k2 &= ~(a.z & bm);
            k3 &= ~(a.w & bm);
        }
        sm.keepw[0] = k0; sm.keepw[1] = k1; sm.keepw[2] = k2; sm.keepw[3] = k3;
    }
    __syncthreads();
    if (tid < TOPK) sm.skeep[tid] = (sm.keepw[tid >> 5] >> (tid & 31)) & 1u;
    __syncthreads();

    // ---- write outputs ----
    constexpr int D = (LEVEL == 2) ? 16 : 4;
    constexpr size_t data_off  = (LEVEL == 0) ? 0      : (LEVEL == 1) ? 38400 : 76800;
    constexpr size_t score_off = (LEVEL == 0) ? 25600  : (LEVEL == 1) ? 64000 : 179200;
    constexpr size_t keep_off  = (LEVEL == 0) ? 32000  : (LEVEL == 1) ? 70400 : 185600;

    float* dp = out + data_off + (size_t)b * TOPK * D;
    const float* sd = (const float*)sm.sdat4;
    for (int idx = tid; idx < TOPK * D; idx += NT) {
        int k = idx / D;
        dp[idx] = sm.skeep[k] ? sd[k * 16 + (idx - k * D)] : 0.0f;
    }
    if (tid < TOPK) {
        out[score_off + (size_t)b * TOPK + tid] = sm.skeep[tid] ? sm.sval[tid] : 0.0f;
        out[keep_off  + (size_t)b * TOPK + tid] = sm.skeep[tid] ? 1.0f : 0.0f;
    }
}

__global__ void __launch_bounds__(NT)
postprocess_kernel(const float* __restrict__ blk_logit,
                   const float* __restrict__ lin_logit,
                   const float* __restrict__ chr_logit,
                   const float* __restrict__ blk_raw,
                   const float* __restrict__ lin_raw,
                   const float* __restrict__ chr_raw,
                   const float* __restrict__ tsz,
                   float* __restrict__ out)
{
    __shared__ SharedState sm;
    const int b     = blockIdx.x;
    const int level = blockIdx.y;
    const int tid   = threadIdx.x;

    if (level == 0) {
        pp_body<8, 0>(sm, b, tid, blk_logit + (size_t)b * NBLK,
                      blk_raw, lin_raw, chr_raw, tsz, out);
    } else if (level == 1) {
        pp_body<32, 1>(sm, b, tid, lin_logit + (size_t)b * NLIN,
                       blk_raw, lin_raw, chr_raw, tsz, out);
    } else {
        pp_body<32, 2>(sm, b, tid, chr_logit + (size_t)b * NCHR,
                       blk_raw, lin_raw, chr_raw, tsz, out);
    }
}

extern "C" void kernel_launch(void* const* d_in, const int* in_sizes, int n_in,
                              void* d_out, int out_size) {
    (void)in_sizes; (void)n_in; (void)out_size;
    postprocess_kernel<<<dim3(B_IMGS, 3), NT>>>(
        (const float*)d_in[0],   // pred_block_logits
        (const float*)d_in[1],   // pred_line_logits
        (const float*)d_in[2],   // pred_char_logits
        (const float*)d_in[3],   // pred_block
        (const float*)d_in[4],   // pred_line
        (const float*)d_in[5],   // pred_char
        (const float*)d_in[6],   // target_sizes
        (float*)d_out);
}

// round 5
// speedup vs baseline: 1.9908x; 1.4015x over previous
#include <cuda_runtime.h>
#include <math.h>

#define B_IMGS   64
#define NBLK     4096
#define NLIN     16384
#define NCHR     16384
#define TOPK     100
#define KSEL     128      // exact top-K superset size by logit
#define MTGT     160      // stop narrowing once survivor count <= this
#define NT       512
#define FASTCAP  512

// Output layout (float32), reference return order (*blk, *lin, *chr):
//  blk_data [64,100,4]  @ 0       blk_scores @ 25600   blk_keep @ 32000
//  lin_data [64,100,4]  @ 38400   lin_scores @ 64000   lin_keep @ 70400
//  chr_data [64,100,16] @ 76800   chr_scores @ 179200  chr_keep @ 185600

struct __align__(16) SharedState {
    unsigned int adj[TOPK][4];          // 16B rows for uint4 scan
    float4 sdat4[TOPK][4];              // data rows (16 floats max)
    float4 sbox4[TOPK];
    unsigned long long fckey[FASTCAP];  // (prob_bits<<32) | ~idx
    unsigned long long wkeys[16];       // per-warp argmax composite keys
    unsigned int ckey[FASTCAP];
    int          cidx[FASTCAP];
    float sval[TOPK];
    int   sidx[TOPK];
    float sarea[TOPK];
    float sbelong[TOPK];
    int   skeep[TOPK];
    unsigned int keepw[4];
    int totals[32];
    int cnt;
    int cnt2;
    int argmax_idx;
};

template<int LOC, int LEVEL>
__device__ __forceinline__ void pp_body(
    SharedState& sm, int b, int tid,
    const float* __restrict__ lb,        // logits for this (b, level)
    const float* __restrict__ blk_raw,
    const float* __restrict__ lin_raw,
    const float* __restrict__ chr_raw,
    const float* __restrict__ tsz,
    float* __restrict__ out)
{
    const int N = LOC * NT;

    // ---- load logits via float4 -> monotone uint keys (registers) ----
    unsigned int lk[LOC];
    {
        const float4* lb4 = (const float4*)lb;
#pragma unroll
        for (int r4 = 0; r4 < LOC / 4; ++r4) {
            float4 v = lb4[tid + r4 * NT];
            unsigned int u0 = __float_as_uint(v.x);
            unsigned int u1 = __float_as_uint(v.y);
            unsigned int u2 = __float_as_uint(v.z);
            unsigned int u3 = __float_as_uint(v.w);
            lk[4 * r4 + 0] = u0 ^ (((unsigned int)((int)u0 >> 31)) | 0x80000000u);
            lk[4 * r4 + 1] = u1 ^ (((unsigned int)((int)u1 >> 31)) | 0x80000000u);
            lk[4 * r4 + 2] = u2 ^ (((unsigned int)((int)u2 >> 31)) | 0x80000000u);
            lk[4 * r4 + 3] = u3 ^ (((unsigned int)((int)u3 >> 31)) | 0x80000000u);
        }
    }

    if (tid < 32) sm.totals[tid] = 0;
    if (tid == 0) { sm.cnt = 0; sm.cnt2 = 0; sm.argmax_idx = 0; }
    __syncthreads();

    // ---- phase 1: bitwise binary search on registers, exit when survivors <= FASTCAP ----
    unsigned int prefix = 0u;
    int cnt_cur = N;
    int bit = 31;
    for (; bit >= 0; --bit) {
        if (cnt_cur <= FASTCAP) break;
        unsigned int cand = prefix | (1u << bit);
        unsigned int c = 0;
#pragma unroll
        for (int r = 0; r < LOC; ++r) c += (lk[r] >= cand) ? 1u : 0u;
        c = __reduce_add_sync(0xFFFFFFFFu, c);
        if ((tid & 31) == 0 && c) atomicAdd(&sm.totals[bit], (int)c);
        __syncthreads();
        int tot = sm.totals[bit];
        if (tot >= KSEL) { prefix = cand; cnt_cur = tot; }
    }

    // ---- phase 2: gather survivors (key >= prefix) to shared ----
#pragma unroll
    for (int r4 = 0; r4 < LOC / 4; ++r4) {
#pragma unroll
        for (int c = 0; c < 4; ++c) {
            unsigned int k = lk[4 * r4 + c];
            if (k >= prefix) {
                int p = atomicAdd(&sm.cnt, 1);
                if (p < FASTCAP) { sm.ckey[p] = k; sm.cidx[p] = 4 * (tid + r4 * NT) + c; }
            }
        }
    }
    __syncthreads();
    const int cg = min(sm.cnt, FASTCAP);
    const unsigned int mykey = (tid < cg) ? sm.ckey[tid] : 0u;
    const int myidx = (tid < cg) ? sm.cidx[tid] : 0;

    // ---- phase 3: continue narrowing until survivor count <= MTGT ----
    int cnt_m = cg;
    for (; bit >= 0 && cnt_m > MTGT; --bit) {
        unsigned int cand = prefix | (1u << bit);
        int c = __syncthreads_count((tid < cg) && (mykey >= cand));
        if (c >= KSEL) { prefix = cand; cnt_m = c; }
    }

    // ---- phase 4: compact final survivors, fast f32 sigmoid, composite key ----
    if (tid < cg && mykey >= prefix) {
        int p = atomicAdd(&sm.cnt2, 1);
        unsigned int u = mykey ^ ((mykey & 0x80000000u) ? 0x80000000u : 0xFFFFFFFFu);
        float x = __uint_as_float(u);
        float prob = 1.0f / (1.0f + __expf(-x));
        sm.fckey[p] = ((unsigned long long)__float_as_uint(prob) << 32)
                      | (unsigned int)(~(unsigned int)myidx);
    }
    __syncthreads();
    const int M = min(sm.cnt2, FASTCAP);   // >= 128 (prefix count >= KSEL)

    // ---- rank by composite key desc == (prob desc, index asc) ----
    if (tid < M) {
        const unsigned long long mk = sm.fckey[tid];
        int rank = 0;
        for (int j = 0; j < M; ++j) rank += (sm.fckey[j] > mk) ? 1 : 0;
        if (rank < TOPK) {
            sm.sval[rank] = __uint_as_float((unsigned int)(mk >> 32));
            sm.sidx[rank] = (int)(~(unsigned int)(mk & 0xFFFFFFFFu));
        }
    }
    __syncthreads();

    const float hh = tsz[2 * b + 0];   // img_h
    const float ww = tsz[2 * b + 1];   // img_w

    // ---- char level: spread scattered ctrl-point gather over 400 threads ----
    if (LEVEL == 2) {
        if (tid < TOPK * 4) {
            const int k = tid >> 2, q = tid & 3;
            const int si = sm.sidx[k];
            float4 v = ((const float4*)(chr_raw + ((size_t)b * NCHR + (size_t)si) * 16))[q];
            v.x *= hh; v.y *= ww; v.z *= hh; v.w *= ww;
            sm.sdat4[k][q] = v;
        }
        __syncthreads();
    }

    // ---- per-detection geometry ----
    if (tid < TOPK) {
        const int k  = tid;
        const int si = sm.sidx[k];
        float x1, y1, x2, y2;
        float4 p;   // parent box raw (lines/chars) — hoisted load

        if (LEVEL == 1) {
            p = ((const float4*)(blk_raw + ((size_t)b * NBLK + (size_t)(si >> 2)) * 4))[0];
        } else if (LEVEL == 2) {
            p = ((const float4*)(lin_raw + ((size_t)b * NLIN + (size_t)si) * 4))[0];
        }

        if (LEVEL == 2) {
            float ctrl[16];
#pragma unroll
            for (int q = 0; q < 4; ++q) {
                float4 v = sm.sdat4[k][q];
                ctrl[4 * q + 0] = v.x; ctrl[4 * q + 1] = v.y;
                ctrl[4 * q + 2] = v.z; ctrl[4 * q + 3] = v.w;
            }
            float mnx = 1e30f, mny = 1e30f, mxx = -1e30f, mxy = -1e30f;
#pragma unroll
            for (int s = 0; s < 10; ++s) {
                float t  = (float)s * (1.0f / 9.0f);
                float ti = 1.0f - t;
                float b0 = ti * ti * ti;
                float b1 = 3.0f * t * ti * ti;
                float b2 = 3.0f * t * t * ti;
                float b3 = t * t * t;
                float xt = b0 * ctrl[0] + b1 * ctrl[2]  + b2 * ctrl[4]  + b3 * ctrl[6];
                float yt = b0 * ctrl[1] + b1 * ctrl[3]  + b2 * ctrl[5]  + b3 * ctrl[7];
                float xb = b0 * ctrl[8] + b1 * ctrl[10] + b2 * ctrl[12] + b3 * ctrl[14];
                float yb = b0 * ctrl[9] + b1 * ctrl[11] + b2 * ctrl[13] + b3 * ctrl[15];
                mnx = fminf(mnx, fminf(xt, xb));
                mny = fminf(mny, fminf(yt, yb));
                mxx = fmaxf(mxx, fmaxf(xt, xb));
                mxy = fmaxf(mxy, fmaxf(yt, yb));
            }
            x1 = mnx; y1 = mny; x2 = mxx; y2 = mxy;
        } else {
            float4 v = (LEVEL == 0)
                ? ((const float4*)(blk_raw + ((size_t)b * NBLK + (size_t)si) * 4))[0]
                : ((const float4*)(lin_raw + ((size_t)b * NLIN + (size_t)si) * 4))[0];
            x1 = (v.x - 0.5f * v.z) * ww;
            y1 = (v.y - 0.5f * v.w) * hh;
            x2 = (v.x + 0.5f * v.z) * ww;
            y2 = (v.y + 0.5f * v.w) * hh;
            if (LEVEL == 0) {
                x1 = fminf(fmaxf(x1, 0.0f), ww);
                y1 = fminf(fmaxf(y1, 0.0f), hh);
                x2 = fminf(fmaxf(x2, 0.0f), ww);
                y2 = fminf(fmaxf(y2, 0.0f), hh);
            }
            float4 d; d.x = x1; d.y = y1; d.z = x2; d.w = y2;
            sm.sdat4[k][0] = d;
        }

        float4 bx; bx.x = x1; bx.y = y1; bx.z = x2; bx.w = y2;
        sm.sbox4[k] = bx;
        sm.sarea[k] = (x2 - x1) * (y2 - y1);

        bool kp   = sm.sval[k] > 0.1f;
        bool anyk = sm.sval[0] > 0.1f;     // desc-sorted => any() == first > thr
        if (!anyk) kp = (k == 0);
        sm.skeep[k] = kp ? 1 : 0;

        if (LEVEL > 0) {
            float px1 = (p.x - 0.5f * p.z) * ww;
            float py1 = (p.y - 0.5f * p.w) * hh;
            float px2 = (p.x + 0.5f * p.z) * ww;
            float py2 = (p.y + 0.5f * p.w) * hh;
            float ix1 = fmaxf(x1, px1);
            float iy1 = fmaxf(y1, py1);
            float ix2 = fminf(x2, px2);
            float iy2 = fminf(y2, py2);
            float inter = fmaxf(ix2 - ix1, 0.0f) * fmaxf(iy2 - iy1, 0.0f);
            float carea = (x2 - x1) * (y2 - y1);
            sm.sbelong[k] = inter / (carea + 1e-6f);
        }
    }
    __syncthreads();

    // ---- belong validity + fallback (lines / chars), parallel argmax ----
    if (LEVEL > 0) {
        const bool in = (tid < TOPK) && (sm.skeep[tid] != 0);
        const float bl = in ? sm.sbelong[tid] : 0.0f;
        // any(valid & keep)
        int any_vk = __syncthreads_count(in && (bl > 0.6f));
        // argmax over where(keep, belong, -inf), first-max-index semantics:
        // composite key (belong_bits<<32)|~tid; key 0 when masked.
        unsigned long long key = in
            ? (((unsigned long long)__float_as_uint(bl) << 32) | (unsigned int)(~(unsigned int)tid))
            : 0ull;
#pragma unroll
        for (int off = 16; off > 0; off >>= 1) {
            unsigned long long o = __shfl_down_sync(0xFFFFFFFFu, key, off);
            key = (o > key) ? o : key;
        }
        if ((tid & 31) == 0) sm.wkeys[tid >> 5] = key;
        __syncthreads();
        if (tid == 0) {
            unsigned long long best = 0ull;
#pragma unroll
            for (int w = 0; w < 16; ++w) best = (sm.wkeys[w] > best) ? sm.wkeys[w] : best;
            // all -inf (no keep) -> jnp.argmax returns 0
            sm.argmax_idx = (best == 0ull) ? 0 : (int)(~(unsigned int)(best & 0xFFFFFFFFu));
        }
        __syncthreads();
        if (tid < TOPK) {
            bool valid = sm.sbelong[tid] > 0.6f;
            if (any_vk == 0) valid = (tid == sm.argmax_idx);
            if (!valid) sm.skeep[tid] = 0;
        }
        __syncthreads();
    }

    // ---- NMS: build adjacency bitmask rows in parallel (skip all-zero words) ----
    {
        const int warp = tid >> 5, lane = tid & 31;
        for (int task = warp; task < TOPK * 4; task += NT / 32) {
            const int i = task >> 2, w = task & 3;
            unsigned int m = 0u;
            if (i < 32 * (w + 1)) {          // word has some j > i
                const int j = w * 32 + lane;
                bool pred = false;
                if (j < TOPK && j > i) {
                    float4 bi_ = sm.sbox4[i];
                    float4 bj_ = sm.sbox4[j];
                    float ix1 = fmaxf(bi_.x, bj_.x);
                    float iy1 = fmaxf(bi_.y, bj_.y);
                    float ix2 = fminf(bi_.z, bj_.z);
                    float iy2 = fminf(bi_.w, bj_.w);
                    float inter = fmaxf(ix2 - ix1, 0.0f) * fmaxf(iy2 - iy1, 0.0f);
                    // iou > 0.1  <=>  inter > 0.1*union   (union >= 0; NaN-safe false)
                    pred = inter > 0.1f * (sm.sarea[i] + sm.sarea[j] - inter);
                }
                m = __ballot_sync(0xFFFFFFFFu, pred);
            }
            if (lane == 0) sm.adj[i][w] = m;
        }
        if (tid < 128) {
            bool kp = (tid < TOPK) && (sm.skeep[tid] != 0);
            unsigned int m = __ballot_sync(0xFFFFFFFFu, kp);
            if ((tid & 31) == 0) sm.keepw[tid >> 5] = m;
        }
    }
    __syncthreads();

    // ---- sequential suppression scan: single thread, uint4 rows, branchless ----
    if (tid == 0) {
        unsigned int k0 = sm.keepw[0], k1 = sm.keepw[1], k2 = sm.keepw[2], k3 = sm.keepw[3];
        const uint4* adj4 = (const uint4*)sm.adj;
#pragma unroll
        for (int i = 0; i < TOPK; ++i) {
            unsigned int ki = (i < 32) ? k0 : (i < 64) ? k1 : (i < 96) ? k2 : k3;
            unsigned int bm = (unsigned int)(-(int)((ki >> (i & 31)) & 1u));
            uint4 a = adj4[i];
            k0 &= ~(a.x & bm);
            k1 &= ~(a.y & bm);
            k2 &= ~(a.z & bm);
            k3 &= ~(a.w & bm);
        }
        sm.keepw[0] = k0; sm.keepw[1] = k1; sm.keepw[2] = k2; sm.keepw[3] = k3;
    }
    __syncthreads();
    if (tid < TOPK) sm.skeep[tid] = (sm.keepw[tid >> 5] >> (tid & 31)) & 1u;
    __syncthreads();

    // ---- write outputs (vectorized data stores) ----
    constexpr size_t data_off  = (LEVEL == 0) ? 0      : (LEVEL == 1) ? 38400 : 76800;
    constexpr size_t score_off = (LEVEL == 0) ? 25600  : (LEVEL == 1) ? 64000 : 179200;
    constexpr size_t keep_off  = (LEVEL == 0) ? 32000  : (LEVEL == 1) ? 70400 : 185600;
    const float4 z4 = make_float4(0.f, 0.f, 0.f, 0.f);

    if (LEVEL == 2) {
        float4* dp4 = (float4*)(out + data_off + (size_t)b * TOPK * 16);
        if (tid < TOPK * 4) {
            const int k = tid >> 2, q = tid & 3;
            dp4[tid] = sm.skeep[k] ? sm.sdat4[k][q] : z4;
        }
    } else {
        float4* dp4 = (float4*)(out + data_off + (size_t)b * TOPK * 4);
        if (tid < TOPK) dp4[tid] = sm.skeep[tid] ? sm.sdat4[tid][0] : z4;
    }
    if (tid < TOPK) {
        out[score_off + (size_t)b * TOPK + tid] = sm.skeep[tid] ? sm.sval[tid] : 0.0f;
        out[keep_off  + (size_t)b * TOPK + tid] = sm.skeep[tid] ? 1.0f : 0.0f;
    }
}

__global__ void __launch_bounds__(NT)
postprocess_kernel(const float* __restrict__ blk_logit,
                   const float* __restrict__ lin_logit,
                   const float* __restrict__ chr_logit,
                   const float* __restrict__ blk_raw,
                   const float* __restrict__ lin_raw,
                   const float* __restrict__ chr_raw,
                   const float* __restrict__ tsz,
                   float* __restrict__ out)
{
    __shared__ SharedState sm;
    const int b     = blockIdx.x;
    const int level = blockIdx.y;
    const int tid   = threadIdx.x;

    if (level == 0) {
        pp_body<8, 0>(sm, b, tid, blk_logit + (size_t)b * NBLK,
                      blk_raw, lin_raw, chr_raw, tsz, out);
    } else if (level == 1) {
        pp_body<32, 1>(sm, b, tid, lin_logit + (size_t)b * NLIN,
                       blk_raw, lin_raw, chr_raw, tsz, out);
    } else {
        pp_body<32, 2>(sm, b, tid, chr_logit + (size_t)b * NCHR,
                       blk_raw, lin_raw, chr_raw, tsz, out);
    }
}

extern "C" void kernel_launch(void* const* d_in, const int* in_sizes, int n_in,
                              void* d_out, int out_size) {
    (void)in_sizes; (void)n_in; (void)out_size;
    postprocess_kernel<<<dim3(B_IMGS, 3), NT>>>(
        (const float*)d_in[0],   // pred_block_logits
        (const float*)d_in[1],   // pred_line_logits
        (const float*)d_in[2],   // pred_char_logits
        (const float*)d_in[3],   // pred_block
        (const float*)d_in[4],   // pred_line
        (const float*)d_in[5],   // pred_char
        (const float*)d_in[6],   // target_sizes
        (float*)d_out);
}

// round 6
// speedup vs baseline: 2.8164x; 1.4147x over previous
#include <cuda_runtime.h>
#include <math.h>

#define B_IMGS   64
#define NBLK     4096
#define NLIN     16384
#define NCHR     16384
#define TOPK     100
#define KSEL     128      // exact top-K superset size by logit
#define MTGT     160      // stop bisection once survivor count <= this
#define NT       512
#define FASTCAP  512

// Output layout (float32), reference return order (*blk, *lin, *chr):
//  blk_data [64,100,4]  @ 0       blk_scores @ 25600   blk_keep @ 32000
//  lin_data [64,100,4]  @ 38400   lin_scores @ 64000   lin_keep @ 70400
//  chr_data [64,100,16] @ 76800   chr_scores @ 179200  chr_keep @ 185600

struct __align__(16) SharedState {
    unsigned int adj[TOPK][4];          // 16B rows for uint4 scan
    float4 sdat4[TOPK][4];              // data rows (16 floats max)
    float4 sbox4[TOPK];
    unsigned long long fckey[FASTCAP];  // (prob_bits<<32) | ~idx ; zero-padded
    unsigned long long wkeys[16];       // per-warp argmax composite keys
    unsigned int ckey[FASTCAP];
    int          cidx[FASTCAP];
    float sval[TOPK];
    int   sidx[TOPK];
    float sarea[TOPK];
    float sbelong[TOPK];
    int   skeep[TOPK];
    int   klist[TOPK];
    unsigned int keepw[4];
    int totals[32];
    int cnt;
    int cnt2;
    int gcnt;
    int kcnt;
    int argmax_idx;
};

template<int LOC, int LEVEL>
__device__ __forceinline__ void pp_body(
    SharedState& sm, int b, int tid,
    const float* __restrict__ lb,        // logits for this (b, level)
    const float* __restrict__ blk_raw,
    const float* __restrict__ lin_raw,
    const float* __restrict__ chr_raw,
    const float* __restrict__ tsz,
    float* __restrict__ out)
{
    const int N = LOC * NT;
    // hard-coded threshold guesses (monotone float->uint keys), per level size
    constexpr unsigned int GK = (LEVEL == 0) ? 0xBFC00000u   // logit 1.5
                                             : 0xC0100000u;  // logit 2.25
    constexpr unsigned int GH = (LEVEL == 0) ? 0xC0800000u   // logit 4.0
                                             : 0xC0980000u;  // logit 4.75

    // ---- load logits via float4 -> monotone uint keys (registers) ----
    unsigned int lk[LOC];
    {
        const float4* lb4 = (const float4*)lb;
#pragma unroll
        for (int r4 = 0; r4 < LOC / 4; ++r4) {
            float4 v = lb4[tid + r4 * NT];
            unsigned int u0 = __float_as_uint(v.x);
            unsigned int u1 = __float_as_uint(v.y);
            unsigned int u2 = __float_as_uint(v.z);
            unsigned int u3 = __float_as_uint(v.w);
            lk[4 * r4 + 0] = u0 ^ (((unsigned int)((int)u0 >> 31)) | 0x80000000u);
            lk[4 * r4 + 1] = u1 ^ (((unsigned int)((int)u1 >> 31)) | 0x80000000u);
            lk[4 * r4 + 2] = u2 ^ (((unsigned int)((int)u2 >> 31)) | 0x80000000u);
            lk[4 * r4 + 3] = u3 ^ (((unsigned int)((int)u3 >> 31)) | 0x80000000u);
        }
    }

    sm.fckey[tid] = 0ull;               // zero-pad for unrolled rank loop
    if (tid < 32) sm.totals[tid] = 0;
    if (tid == 0) { sm.cnt = 0; sm.cnt2 = 0; sm.gcnt = 0; sm.kcnt = 0; sm.argmax_idx = 0; }
    __syncthreads();

    // ---- guess pass: one exact count against GK ----
    {
        unsigned int c = 0;
#pragma unroll
        for (int r = 0; r < LOC; ++r) c += (lk[r] >= GK) ? 1u : 0u;
        c = __reduce_add_sync(0xFFFFFFFFu, c);
        if ((tid & 31) == 0 && c) atomicAdd(&sm.gcnt, (int)c);
    }
    __syncthreads();
    const int cG = sm.gcnt;

    unsigned int prefix, hi;
    int cnt_cur;
    if (cG >= KSEL && cG <= FASTCAP) {
        prefix = GK; hi = GH; cnt_cur = cG;
    } else {
        // ---- fallback: exact bitwise binary search (rare; correctness net) ----
        prefix = 0u; cnt_cur = N;
        for (int bit = 31; bit >= 0; --bit) {
            if (cnt_cur <= FASTCAP) break;
            unsigned int cand = prefix | (1u << bit);
            unsigned int c = 0;
#pragma unroll
            for (int r = 0; r < LOC; ++r) c += (lk[r] >= cand) ? 1u : 0u;
            c = __reduce_add_sync(0xFFFFFFFFu, c);
            if ((tid & 31) == 0 && c) atomicAdd(&sm.totals[bit], (int)c);
            __syncthreads();
            int tot = sm.totals[bit];
            if (tot >= KSEL) { prefix = cand; cnt_cur = tot; }
        }
        hi = 0xFFFFFFFFu;
    }

    // ---- gather survivors (key >= prefix) to shared, 1/thread ----
#pragma unroll
    for (int r4 = 0; r4 < LOC / 4; ++r4) {
#pragma unroll
        for (int c = 0; c < 4; ++c) {
            unsigned int k = lk[4 * r4 + c];
            if (k >= prefix) {
                int p = atomicAdd(&sm.cnt, 1);
                if (p < FASTCAP) { sm.ckey[p] = k; sm.cidx[p] = 4 * (tid + r4 * NT) + c; }
            }
        }
    }
    __syncthreads();
    const int cg = min(sm.cnt, FASTCAP);
    const unsigned int mykey = (tid < cg) ? sm.ckey[tid] : 0u;
    const int myidx = (tid < cg) ? sm.cidx[tid] : 0;

    // ---- value bisection: shrink survivor count toward [KSEL, MTGT] ----
    unsigned int lo = prefix;
    int cnt_m = cnt_cur;
    for (int it = 0; it < 6 && cnt_m > MTGT; ++it) {
        unsigned int mid = lo + ((hi - lo) >> 1);
        int c = __syncthreads_count((tid < cg) && (mykey >= mid));
        if (c >= KSEL) { lo = mid; cnt_m = c; } else hi = mid;
    }

    // ---- compact final survivors, fast f32 sigmoid, composite key ----
    if (tid < cg && mykey >= lo) {
        int p = atomicAdd(&sm.cnt2, 1);
        unsigned int u = mykey ^ ((mykey & 0x80000000u) ? 0x80000000u : 0xFFFFFFFFu);
        float x = __uint_as_float(u);
        float prob = 1.0f / (1.0f + __expf(-x));
        sm.fckey[p] = ((unsigned long long)__float_as_uint(prob) << 32)
                      | (unsigned int)(~(unsigned int)myidx);
    }
    __syncthreads();
    const int M = min(sm.cnt2, FASTCAP);   // >= KSEL (count(>=lo) >= KSEL)

    // ---- rank by composite key desc == (prob desc, index asc); x4 unrolled ----
    if (tid < M) {
        const unsigned long long mk = sm.fckey[tid];
        int rank = 0;
        const int Mp = (M + 3) & ~3;       // padded slots are 0 and never > mk
        for (int j = 0; j < Mp; j += 4) {
            rank += (sm.fckey[j]     > mk) ? 1 : 0;
            rank += (sm.fckey[j + 1] > mk) ? 1 : 0;
            rank += (sm.fckey[j + 2] > mk) ? 1 : 0;
            rank += (sm.fckey[j + 3] > mk) ? 1 : 0;
        }
        if (rank < TOPK) {
            sm.sval[rank] = __uint_as_float((unsigned int)(mk >> 32));
            sm.sidx[rank] = (int)(~(unsigned int)(mk & 0xFFFFFFFFu));
        }
    }
    __syncthreads();

    const float hh = tsz[2 * b + 0];   // img_h
    const float ww = tsz[2 * b + 1];   // img_w

    // ---- char level: spread scattered ctrl-point gather over 400 threads ----
    if (LEVEL == 2) {
        if (tid < TOPK * 4) {
            const int k = tid >> 2, q = tid & 3;
            const int si = sm.sidx[k];
            float4 v = ((const float4*)(chr_raw + ((size_t)b * NCHR + (size_t)si) * 16))[q];
            v.x *= hh; v.y *= ww; v.z *= hh; v.w *= ww;
            sm.sdat4[k][q] = v;
        }
        __syncthreads();
    }

    // ---- per-detection geometry ----
    if (tid < TOPK) {
        const int k  = tid;
        const int si = sm.sidx[k];
        float x1, y1, x2, y2;
        float4 p;   // parent box raw (lines/chars) — hoisted load

        if (LEVEL == 1) {
            p = ((const float4*)(blk_raw + ((size_t)b * NBLK + (size_t)(si >> 2)) * 4))[0];
        } else if (LEVEL == 2) {
            p = ((const float4*)(lin_raw + ((size_t)b * NLIN + (size_t)si) * 4))[0];
        }

        if (LEVEL == 2) {
            float ctrl[16];
#pragma unroll
            for (int q = 0; q < 4; ++q) {
                float4 v = sm.sdat4[k][q];
                ctrl[4 * q + 0] = v.x; ctrl[4 * q + 1] = v.y;
                ctrl[4 * q + 2] = v.z; ctrl[4 * q + 3] = v.w;
            }
            float mnx = 1e30f, mny = 1e30f, mxx = -1e30f, mxy = -1e30f;
#pragma unroll
            for (int s = 0; s < 10; ++s) {
                float t  = (float)s * (1.0f / 9.0f);
                float ti = 1.0f - t;
                float b0 = ti * ti * ti;
                float b1 = 3.0f * t * ti * ti;
                float b2 = 3.0f * t * t * ti;
                float b3 = t * t * t;
                float xt = b0 * ctrl[0] + b1 * ctrl[2]  + b2 * ctrl[4]  + b3 * ctrl[6];
                float yt = b0 * ctrl[1] + b1 * ctrl[3]  + b2 * ctrl[5]  + b3 * ctrl[7];
                float xb = b0 * ctrl[8] + b1 * ctrl[10] + b2 * ctrl[12] + b3 * ctrl[14];
                float yb = b0 * ctrl[9] + b1 * ctrl[11] + b2 * ctrl[13] + b3 * ctrl[15];
                mnx = fminf(mnx, fminf(xt, xb));
                mny = fminf(mny, fminf(yt, yb));
                mxx = fmaxf(mxx, fmaxf(xt, xb));
                mxy = fmaxf(mxy, fmaxf(yt, yb));
            }
            x1 = mnx; y1 = mny; x2 = mxx; y2 = mxy;
        } else {
            float4 v = (LEVEL == 0)
                ? ((const float4*)(blk_raw + ((size_t)b * NBLK + (size_t)si) * 4))[0]
                : ((const float4*)(lin_raw + ((size_t)b * NLIN + (size_t)si) * 4))[0];
            x1 = (v.x - 0.5f * v.z) * ww;
            y1 = (v.y - 0.5f * v.w) * hh;
            x2 = (v.x + 0.5f * v.z) * ww;
            y2 = (v.y + 0.5f * v.w) * hh;
            if (LEVEL == 0) {
                x1 = fminf(fmaxf(x1, 0.0f), ww);
                y1 = fminf(fmaxf(y1, 0.0f), hh);
                x2 = fminf(fmaxf(x2, 0.0f), ww);
                y2 = fminf(fmaxf(y2, 0.0f), hh);
            }
            float4 d; d.x = x1; d.y = y1; d.z = x2; d.w = y2;
            sm.sdat4[k][0] = d;
        }

        float4 bx; bx.x = x1; bx.y = y1; bx.z = x2; bx.w = y2;
        sm.sbox4[k] = bx;
        sm.sarea[k] = (x2 - x1) * (y2 - y1);

        bool kp   = sm.sval[k] > 0.1f;
        bool anyk = sm.sval[0] > 0.1f;     // desc-sorted => any() == first > thr
        if (!anyk) kp = (k == 0);
        sm.skeep[k] = kp ? 1 : 0;

        if (LEVEL > 0) {
            float px1 = (p.x - 0.5f * p.z) * ww;
            float py1 = (p.y - 0.5f * p.w) * hh;
            float px2 = (p.x + 0.5f * p.z) * ww;
            float py2 = (p.y + 0.5f * p.w) * hh;
            float ix1 = fmaxf(x1, px1);
            float iy1 = fmaxf(y1, py1);
            float ix2 = fminf(x2, px2);
            float iy2 = fminf(y2, py2);
            float inter = fmaxf(ix2 - ix1, 0.0f) * fmaxf(iy2 - iy1, 0.0f);
            float carea = (x2 - x1) * (y2 - y1);
            sm.sbelong[k] = inter / (carea + 1e-6f);
        }
    }
    __syncthreads();

    // ---- belong validity + fallback (lines / chars), parallel argmax ----
    if (LEVEL > 0) {
        const bool in = (tid < TOPK) && (sm.skeep[tid] != 0);
        const float bl = in ? sm.sbelong[tid] : 0.0f;
        int any_vk = __syncthreads_count(in && (bl > 0.6f));
        unsigned long long key = in
            ? (((unsigned long long)__float_as_uint(bl) << 32) | (unsigned int)(~(unsigned int)tid))
            : 0ull;
#pragma unroll
        for (int off = 16; off > 0; off >>= 1) {
            unsigned long long o = __shfl_down_sync(0xFFFFFFFFu, key, off);
            key = (o > key) ? o : key;
        }
        if ((tid & 31) == 0) sm.wkeys[tid >> 5] = key;
        __syncthreads();
        if (tid == 0) {
            unsigned long long best = 0ull;
#pragma unroll
            for (int w = 0; w < 16; ++w) best = (sm.wkeys[w] > best) ? sm.wkeys[w] : best;
            sm.argmax_idx = (best == 0ull) ? 0 : (int)(~(unsigned int)(best & 0xFFFFFFFFu));
        }
        __syncthreads();
        if (tid < TOPK) {
            bool valid = sm.sbelong[tid] > 0.6f;
            if (any_vk == 0) valid = (tid == sm.argmax_idx);
            if (!valid) sm.skeep[tid] = 0;
        }
        __syncthreads();
    }

    // ---- keep ballot + compact kept-index list ----
    if (tid < 128) {
        bool kp = (tid < TOPK) && (sm.skeep[tid] != 0);
        unsigned int m = __ballot_sync(0xFFFFFFFFu, kp);
        if ((tid & 31) == 0) sm.keepw[tid >> 5] = m;
    }
    if (tid < TOPK && sm.skeep[tid]) {
        int p = atomicAdd(&sm.kcnt, 1);
        sm.klist[p] = tid;
    }
    __syncthreads();

    // ---- NMS adjacency: only rows for initially-kept boxes ----
    {
        const int warp = tid >> 5, lane = tid & 31;
        const int ntask = sm.kcnt * 4;
        for (int task = warp; task < ntask; task += NT / 32) {
            const int i = sm.klist[task >> 2], w = task & 3;
            unsigned int m = 0u;
            if (i < 32 * (w + 1)) {          // word has some j > i
                const int j = w * 32 + lane;
                bool pred = false;
                if (j < TOPK && j > i) {
                    float4 bi_ = sm.sbox4[i];
                    float4 bj_ = sm.sbox4[j];
                    float ix1 = fmaxf(bi_.x, bj_.x);
                    float iy1 = fmaxf(bi_.y, bj_.y);
                    float ix2 = fminf(bi_.z, bj_.z);
                    float iy2 = fminf(bi_.w, bj_.w);
                    float inter = fmaxf(ix2 - ix1, 0.0f) * fmaxf(iy2 - iy1, 0.0f);
                    // iou > 0.1 <=> inter > 0.1*union (union >= 0; NaN-safe false)
                    pred = inter > 0.1f * (sm.sarea[i] + sm.sarea[j] - inter);
                }
                m = __ballot_sync(0xFFFFFFFFu, pred);
            }
            if (lane == 0) sm.adj[i][w] = m;
        }
    }
    __syncthreads();

    // ---- suppression scan: ffs-jump over still-kept boxes only ----
    if (tid == 0) {
        unsigned int kk0 = sm.keepw[0], kk1 = sm.keepw[1], kk2 = sm.keepw[2], kk3 = sm.keepw[3];
        const uint4* adj4 = (const uint4*)sm.adj;
#pragma unroll
        for (int w = 0; w < 4; ++w) {
            unsigned int cur = (w == 0) ? kk0 : (w == 1) ? kk1 : (w == 2) ? kk2 : kk3;
            unsigned int m = cur;
            while (m) {
                int bitp = __ffs(m) - 1;
                int i = 32 * w + bitp;
                uint4 a = adj4[i];                    // row has only j > i
                kk0 &= ~a.x; kk1 &= ~a.y; kk2 &= ~a.z; kk3 &= ~a.w;
                cur = (w == 0) ? kk0 : (w == 1) ? kk1 : (w == 2) ? kk2 : kk3;
                m = cur & ((0xFFFFFFFFu << bitp) << 1);   // strictly above bitp (<<32-safe)
            }
        }
        sm.keepw[0] = kk0; sm.keepw[1] = kk1; sm.keepw[2] = kk2; sm.keepw[3] = kk3;
    }
    __syncthreads();

    // ---- write outputs (keep bits read directly from keepw) ----
    constexpr size_t data_off  = (LEVEL == 0) ? 0      : (LEVEL == 1) ? 38400 : 76800;
    constexpr size_t score_off = (LEVEL == 0) ? 25600  : (LEVEL == 1) ? 64000 : 179200;
    constexpr size_t keep_off  = (LEVEL == 0) ? 32000  : (LEVEL == 1) ? 70400 : 185600;
    const float4 z4 = make_float4(0.f, 0.f, 0.f, 0.f);

    if (LEVEL == 2) {
        float4* dp4 = (float4*)(out + data_off + (size_t)b * TOPK * 16);
        if (tid < TOPK * 4) {
            const int k = tid >> 2, q = tid & 3;
            bool kp = (sm.keepw[k >> 5] >> (k & 31)) & 1u;
            dp4[tid] = kp ? sm.sdat4[k][q] : z4;
        }
    } else {
        float4* dp4 = (float4*)(out + data_off + (size_t)b * TOPK * 4);
        if (tid < TOPK) {
            bool kp = (sm.keepw[tid >> 5] >> (tid & 31)) & 1u;
            dp4[tid] = kp ? sm.sdat4[tid][0] : z4;
        }
    }
    if (tid < TOPK) {
        bool kp = (sm.keepw[tid >> 5] >> (tid & 31)) & 1u;
        out[score_off + (size_t)b * TOPK + tid] = kp ? sm.sval[tid] : 0.0f;
        out[keep_off  + (size_t)b * TOPK + tid] = kp ? 1.0f : 0.0f;
    }
}

__global__ void __launch_bounds__(NT)
postprocess_kernel(const float* __restrict__ blk_logit,
                   const float* __restrict__ lin_logit,
                   const float* __restrict__ chr_logit,
                   const float* __restrict__ blk_raw,
                   const float* __restrict__ lin_raw,
                   const float* __restrict__ chr_raw,
                   const float* __restrict__ tsz,
                   float* __restrict__ out)
{
    __shared__ SharedState sm;
    const int b     = blockIdx.x;
    const int level = blockIdx.y;
    const int tid   = threadIdx.x;

    if (level == 0) {
        pp_body<8, 0>(sm, b, tid, blk_logit + (size_t)b * NBLK,
                      blk_raw, lin_raw, chr_raw, tsz, out);
    } else if (level == 1) {
        pp_body<32, 1>(sm, b, tid, lin_logit + (size_t)b * NLIN,
                       blk_raw, lin_raw, chr_raw, tsz, out);
    } else {
        pp_body<32, 2>(sm, b, tid, chr_logit + (size_t)b * NCHR,
                       blk_raw, lin_raw, chr_raw, tsz, out);
    }
}

extern "C" void kernel_launch(void* const* d_in, const int* in_sizes, int n_in,
                              void* d_out, int out_size) {
    (void)in_sizes; (void)n_in; (void)out_size;
    postprocess_kernel<<<dim3(B_IMGS, 3), NT>>>(
        (const float*)d_in[0],   // pred_block_logits
        (const float*)d_in[1],   // pred_line_logits
        (const float*)d_in[2],   // pred_char_logits
        (const float*)d_in[3],   // pred_block
        (const float*)d_in[4],   // pred_line
        (const float*)d_in[5],   // pred_char
        (const float*)d_in[6],   // target_sizes
        (float*)d_out);
}